// round 6
// baseline (speedup 1.0000x reference)
#include <cuda_runtime.h>
#include <cuda_bf16.h>
#include <math.h>
#include <stdint.h>

// ---------------------------------------------------------------------------
//   s       = sum(target^2);  W[i] = rowsum(W_beta);  scale_i = W^2/(s W^2+1)
//   G       = source @ target^T          -> Wm = scale[:,None]*G  (GEMM 1)
//   primary = Wm @ target - source       (GEMM 2, B = pre-transposed target,
//                                         result stored transposed)
//   loss    = sqrt(||W_beta @ primary||^2)  (GEMM 3, Z never stored)
// GEMMs: D[m,n] = sum_k A[m,k]*B[n,k], K-major operands, bf16x3 split on
// mma.sync.m16n8k16 (sm_80 base ISA; tcgen05 unavailable at compute_103).
// R5->R6: split passes hoisted outermost (kills back-to-back RAW on the same
// HMMA accumulator); next-stage STS interleaved between MMA passes.
// ---------------------------------------------------------------------------

#define PMAX 4096
__device__ float  g_Wm [(size_t)PMAX * PMAX];
__device__ float  g_PrT[(size_t)PMAX * PMAX];
__device__ float  g_Tt [(size_t)PMAX * PMAX];
__device__ float  g_W[PMAX];
__device__ double g_s;
__device__ double g_ss;

__device__ __forceinline__ uint32_t smem_u32(const void* p) {
    uint32_t a;
    asm("{ .reg .u64 t; cvta.to.shared.u64 t, %1; cvt.u32.u64 %0, t; }"
        : "=r"(a) : "l"(p));
    return a;
}

__device__ __forceinline__ void ldsm4(uint32_t* r, uint32_t addr) {
    asm volatile("ldmatrix.sync.aligned.m8n8.x4.shared.b16 {%0,%1,%2,%3}, [%4];"
        : "=r"(r[0]), "=r"(r[1]), "=r"(r[2]), "=r"(r[3]) : "r"(addr));
}

__device__ __forceinline__ void mma_bf16(float* c, const uint32_t* a,
                                         const uint32_t* b) {
    asm volatile(
        "mma.sync.aligned.m16n8k16.row.col.f32.bf16.bf16.f32 "
        "{%0,%1,%2,%3}, {%4,%5,%6,%7}, {%8,%9}, {%0,%1,%2,%3};"
        : "+f"(c[0]), "+f"(c[1]), "+f"(c[2]), "+f"(c[3])
        : "r"(a[0]), "r"(a[1]), "r"(a[2]), "r"(a[3]), "r"(b[0]), "r"(b[1]));
}

__device__ __forceinline__ void split2(float x, float y, uint32_t& h, uint32_t& l) {
    __nv_bfloat162 hp = __floats2bfloat162_rn(x, y);
    float rx = x - __low2float(hp);
    float ry = y - __high2float(hp);
    __nv_bfloat162 lp = __floats2bfloat162_rn(rx, ry);
    h = *reinterpret_cast<uint32_t*>(&hp);
    l = *reinterpret_cast<uint32_t*>(&lp);
}

#define STS64(addr, r0, r1) \
    asm volatile("st.shared.v2.b32 [%0], {%1,%2};" \
        :: "r"(addr), "r"(r0), "r"(r1) : "memory")

// ---------------- small kernels ------------------------------------------
__global__ void init_kernel() { g_s = 0.0; g_ss = 0.0; }

__device__ __forceinline__ float blockReduceSum(float v) {
    __shared__ float sh[32];
    int lane = threadIdx.x & 31, wid = threadIdx.x >> 5;
#pragma unroll
    for (int o = 16; o; o >>= 1) v += __shfl_down_sync(0xffffffffu, v, o);
    if (lane == 0) sh[wid] = v;
    __syncthreads();
    int nw = (blockDim.x + 31) >> 5;
    v = (threadIdx.x < nw) ? sh[threadIdx.x] : 0.0f;
    if (wid == 0)
#pragma unroll
        for (int o = 16; o; o >>= 1) v += __shfl_down_sync(0xffffffffu, v, o);
    return v;
}

__global__ void sumsq_kernel(const float* __restrict__ X, size_t n) {
    float local = 0.0f;
    for (size_t i = (size_t)blockIdx.x * blockDim.x + threadIdx.x; i < n;
         i += (size_t)gridDim.x * blockDim.x) {
        float v = X[i];
        local += v * v;
    }
    float b = blockReduceSum(local);
    if (threadIdx.x == 0) atomicAdd(&g_s, (double)b);
}

__global__ void rowsum_kernel(const float* __restrict__ Wb, int P) {
    const float* r = Wb + (size_t)blockIdx.x * P;
    float local = 0.0f;
    for (int j = threadIdx.x; j < P; j += blockDim.x) local += r[j];
    float b = blockReduceSum(local);
    if (threadIdx.x == 0) g_W[blockIdx.x] = b;
}

__global__ void transpose_kernel(const float* __restrict__ in,
                                 float* __restrict__ out, int P) {
    __shared__ float tile[32][33];
    int tx = threadIdx.x, ty = threadIdx.y;
    int x = blockIdx.x * 32 + tx;
    int y0 = blockIdx.y * 32;
#pragma unroll
    for (int j = 0; j < 32; j += 8)
        tile[ty + j][tx] = in[(size_t)(y0 + ty + j) * P + x];
    __syncthreads();
    int xo = blockIdx.y * 32 + tx;
    int yo0 = blockIdx.x * 32;
#pragma unroll
    for (int j = 0; j < 32; j += 8)
        out[(size_t)(yo0 + ty + j) * P + xo] = tile[tx][ty + j];
}

__global__ void finalize_kernel(float* __restrict__ out) {
    out[0] = (float)sqrt(g_ss);
}

// ---------------- mma.sync GEMM ------------------------------------------
// Block 128x128, BK=32, 256 threads = 8 warps in 4(M) x 2(N); warp tile 32x64.
// SMEM stage: Ahi|Alo|Bhi|Blo, each 128 rows x 40 bf16 (80B padded) = 10240B.
#define BM 128
#define BN 128
#define BK 32
#define ROWB 80
#define TILEB (128 * ROWB)     // 10240
#define STAGEB (4 * TILEB)     // 40960
#define SMEM_SZ (2 * STAGEB)   // 81920 (epilogue staging overlays this)

// MODE 1: D *= scale[row]; -> O0 (g_Wm) + optional O1 (d_out, maybe unaligned)
// MODE 2: D -= aux;  store transposed -> O0 (g_PrT)
// MODE 3: g_ss += sum(D^2)
template <int MODE>
__global__ __launch_bounds__(256, 1) void gemm_mma(
    const float* __restrict__ A, const float* __restrict__ B,
    const float* __restrict__ aux, float* __restrict__ O0,
    float* __restrict__ O1, int P)
{
    extern __shared__ char smraw[];
    const uint32_t sb = smem_u32(smraw);

    const int tid = threadIdx.x, lane = tid & 31, wid = tid >> 5;
    const int wm = wid >> 1, wn = wid & 1;
    const int bx = blockIdx.x, by = blockIdx.y;

    const float* Ab = A + (size_t)(by * BM) * P;
    const float* Bb = B + (size_t)(bx * BN) * P;
    const int iters = P / BK;

    float acc[2][8][4];
#pragma unroll
    for (int mt = 0; mt < 2; mt++)
#pragma unroll
        for (int nt = 0; nt < 8; nt++)
#pragma unroll
            for (int i = 0; i < 4; i++) acc[mt][nt][i] = 0.0f;

    const int lrow = tid >> 3;     // base row (0..31), +32*i
    const int lkg  = tid & 7;      // k-group (float4 index)

    const int a_row  = wm * 32 + (lane & 15);
    const int a_koff = (lane >> 4) << 3;
    const int b_n    = wn * 64 + ((lane >> 4) << 3) + (lane & 7);
    const int b_koff = ((lane >> 3) & 1) << 3;

    float4 pa[4], pb[4];
#pragma unroll
    for (int i = 0; i < 4; i++) {
        pa[i] = *(const float4*)(Ab + (size_t)(lrow + 32 * i) * P + lkg * 4);
        pb[i] = *(const float4*)(Bb + (size_t)(lrow + 32 * i) * P + lkg * 4);
    }
    // store stage 0
    {
        const uint32_t st = sb;
#pragma unroll
        for (int i = 0; i < 4; i++) {
            uint32_t off = (uint32_t)((lrow + 32 * i) * ROWB + lkg * 8);
            uint32_t h0, l0, h1, l1;
            split2(pa[i].x, pa[i].y, h0, l0);
            split2(pa[i].z, pa[i].w, h1, l1);
            STS64(st + off, h0, h1);
            STS64(st + TILEB + off, l0, l1);
            split2(pb[i].x, pb[i].y, h0, l0);
            split2(pb[i].z, pb[i].w, h1, l1);
            STS64(st + 2 * TILEB + off, h0, h1);
            STS64(st + 3 * TILEB + off, l0, l1);
        }
    }
    __syncthreads();

    for (int t = 0; t < iters; ++t) {
        const uint32_t stage = sb + (uint32_t)((t & 1) * STAGEB);
        const bool havenext = (t + 1 < iters);
        if (havenext) {
            const int k0 = (t + 1) * BK;
#pragma unroll
            for (int i = 0; i < 4; i++) {
                pa[i] = *(const float4*)(Ab + (size_t)(lrow + 32 * i) * P + k0 + lkg * 4);
                pb[i] = *(const float4*)(Bb + (size_t)(lrow + 32 * i) * P + k0 + lkg * 4);
            }
        }
#pragma unroll
        for (int ch = 0; ch < 2; ch++) {
            uint32_t Ah[2][4], Al[2][4], Bh[8][2], Bl[8][2];
#pragma unroll
            for (int mt = 0; mt < 2; mt++) {
                uint32_t addr = stage +
                    (uint32_t)((a_row + mt * 16) * ROWB + (ch * 16 + a_koff) * 2);
                ldsm4(Ah[mt], addr);
                ldsm4(Al[mt], addr + TILEB);
            }
#pragma unroll
            for (int q = 0; q < 4; q++) {
                uint32_t addr = stage + 2 * TILEB +
                    (uint32_t)((b_n + q * 16) * ROWB + (ch * 16 + b_koff) * 2);
                uint32_t r[4];
                ldsm4(r, addr);
                Bh[q * 2][0] = r[0]; Bh[q * 2][1] = r[1];
                Bh[q * 2 + 1][0] = r[2]; Bh[q * 2 + 1][1] = r[3];
                ldsm4(r, addr + TILEB);
                Bl[q * 2][0] = r[0]; Bl[q * 2][1] = r[1];
                Bl[q * 2 + 1][0] = r[2]; Bl[q * 2 + 1][1] = r[3];
            }
            // pass 1: hi*hi  (16 independent accumulators -> no RAW stalls)
#pragma unroll
            for (int mt = 0; mt < 2; mt++)
#pragma unroll
                for (int nt = 0; nt < 8; nt++)
                    mma_bf16(acc[mt][nt], Ah[mt], Bh[nt]);
            // hide next-stage STS under the MMA stream (once, during ch 0)
            if (ch == 0 && havenext) {
                const uint32_t st = sb + (uint32_t)(((t + 1) & 1) * STAGEB);
#pragma unroll
                for (int i = 0; i < 4; i++) {
                    uint32_t off = (uint32_t)((lrow + 32 * i) * ROWB + lkg * 8);
                    uint32_t h0, l0, h1, l1;
                    split2(pa[i].x, pa[i].y, h0, l0);
                    split2(pa[i].z, pa[i].w, h1, l1);
                    STS64(st + off, h0, h1);
                    STS64(st + TILEB + off, l0, l1);
                    split2(pb[i].x, pb[i].y, h0, l0);
                    split2(pb[i].z, pb[i].w, h1, l1);
                    STS64(st + 2 * TILEB + off, h0, h1);
                    STS64(st + 3 * TILEB + off, l0, l1);
                }
            }
            // pass 2: hi*lo
#pragma unroll
            for (int mt = 0; mt < 2; mt++)
#pragma unroll
                for (int nt = 0; nt < 8; nt++)
                    mma_bf16(acc[mt][nt], Ah[mt], Bl[nt]);
            // pass 3: lo*hi
#pragma unroll
            for (int mt = 0; mt < 2; mt++)
#pragma unroll
                for (int nt = 0; nt < 8; nt++)
                    mma_bf16(acc[mt][nt], Al[mt], Bh[nt]);
        }
        __syncthreads();
    }

    // ----------------- epilogues -----------------
    float* smC = (float*)smraw;          // [128][129] fp32 (overlays stages)

    if (MODE == 3) {
        float local = 0.0f;
#pragma unroll
        for (int mt = 0; mt < 2; mt++)
#pragma unroll
            for (int nt = 0; nt < 8; nt++)
#pragma unroll
                for (int i = 0; i < 4; i++)
                    local += acc[mt][nt][i] * acc[mt][nt][i];
        float bsum = blockReduceSum(local);
        if (tid == 0) atomicAdd(&g_ss, (double)bsum);
        return;
    }

#pragma unroll
    for (int mt = 0; mt < 2; mt++)
#pragma unroll
        for (int nt = 0; nt < 8; nt++) {
            int r0 = wm * 32 + mt * 16 + (lane >> 2);
            int c0 = wn * 64 + nt * 8 + (lane & 3) * 2;
            smC[r0 * 129 + c0]           = acc[mt][nt][0];
            smC[r0 * 129 + c0 + 1]       = acc[mt][nt][1];
            smC[(r0 + 8) * 129 + c0]     = acc[mt][nt][2];
            smC[(r0 + 8) * 129 + c0 + 1] = acc[mt][nt][3];
        }
    __syncthreads();

    if (MODE == 1) {
        const double s = g_s;
        for (int it = 0; it < 16; it++) {
            int f = it * 256 + tid;
            int row = f >> 5, c4 = (f & 31) * 4;
            double w = (double)g_W[by * BM + row];
            double w2 = w * w;
            float sc = (float)(w2 / (s * w2 + 1.0));
            float4 v;
            v.x = smC[row * 129 + c4] * sc;
            v.y = smC[row * 129 + c4 + 1] * sc;
            v.z = smC[row * 129 + c4 + 2] * sc;
            v.w = smC[row * 129 + c4 + 3] * sc;
            size_t gi = (size_t)(by * BM + row) * P + bx * BN + c4;
            *(float4*)(O0 + gi) = v;
            if (O1) {
                O1[gi] = v.x; O1[gi + 1] = v.y; O1[gi + 2] = v.z; O1[gi + 3] = v.w;
            }
        }
    } else { // MODE 2: subtract aux, store transposed
        for (int it = 0; it < 16; it++) {
            int f = it * 256 + tid;
            int row = f >> 5, c4 = (f & 31) * 4;
            float4 sv = *(const float4*)(aux + (size_t)(by * BM + row) * P + bx * BN + c4);
            smC[row * 129 + c4]     -= sv.x;
            smC[row * 129 + c4 + 1] -= sv.y;
            smC[row * 129 + c4 + 2] -= sv.z;
            smC[row * 129 + c4 + 3] -= sv.w;
        }
        __syncthreads();
        for (int it = 0; it < 16; it++) {
            int f = it * 256 + tid;
            int n = f >> 5, m4 = (f & 31) * 4;
            float4 v;
            v.x = smC[(m4 + 0) * 129 + n];
            v.y = smC[(m4 + 1) * 129 + n];
            v.z = smC[(m4 + 2) * 129 + n];
            v.w = smC[(m4 + 3) * 129 + n];
            *(float4*)(O0 + (size_t)(bx * BN + n) * P + by * BM + m4) = v;
        }
    }
}

// ---------------- launch ---------------------------------------------------
extern "C" void kernel_launch(void* const* d_in, const int* in_sizes, int n_in,
                              void* d_out, int out_size)
{
    const float* target = (const float*)d_in[0];
    const float* source = (const float*)d_in[1];
    const float* Wb     = (const float*)d_in[2];
    float* out = (float*)d_out;

    int P = (int)(sqrt((double)in_sizes[0]) + 0.5);
    size_t pp = (size_t)P * P;

    bool has_matrix = (size_t)out_size >= pp;
    bool has_loss   = ((size_t)out_size != pp);
    float* outW = has_matrix ? (out + (out_size - (int)pp)) : nullptr;

    float* wm  = nullptr; cudaGetSymbolAddress((void**)&wm,  g_Wm);
    float* prT = nullptr; cudaGetSymbolAddress((void**)&prT, g_PrT);
    float* tt  = nullptr; cudaGetSymbolAddress((void**)&tt,  g_Tt);

    cudaFuncSetAttribute(gemm_mma<1>, cudaFuncAttributeMaxDynamicSharedMemorySize, SMEM_SZ);
    cudaFuncSetAttribute(gemm_mma<2>, cudaFuncAttributeMaxDynamicSharedMemorySize, SMEM_SZ);
    cudaFuncSetAttribute(gemm_mma<3>, cudaFuncAttributeMaxDynamicSharedMemorySize, SMEM_SZ);

    init_kernel<<<1, 1>>>();
    sumsq_kernel<<<2048, 256>>>(target, pp);
    rowsum_kernel<<<P, 256>>>(Wb, P);
    transpose_kernel<<<dim3(P / 32, P / 32), dim3(32, 8)>>>(target, tt, P);

    dim3 grid(P / BN, P / BM);
    // Wm = scale .* (source @ target^T)
    gemm_mma<1><<<grid, 256, SMEM_SZ>>>(source, target, nullptr, wm, outW, P);
    // primary^T = (Wm @ target - source)^T
    gemm_mma<2><<<grid, 256, SMEM_SZ>>>(wm, tt, source, prT, nullptr, P);
    // ss += ||W_beta @ primary||^2
    gemm_mma<3><<<grid, 256, SMEM_SZ>>>(Wb, prT, nullptr, nullptr, nullptr, P);

    if (has_loss) finalize_kernel<<<1, 1>>>(out);
}

// round 7
// speedup vs baseline: 1.6095x; 1.6095x over previous
#include <cuda_runtime.h>
#include <cuda_bf16.h>
#include <math.h>
#include <stdint.h>

// ---------------------------------------------------------------------------
//   s       = sum(target^2);  W[i] = rowsum(W_beta);  scale_i = W^2/(s W^2+1)
//   GEMM1:  Wm = scale .* (source @ target^T)   -- bf16x3 (3-pass), output
//   GEMM2:  primary = Wm @ target - source      -- single-pass bf16 (feeds loss
//            only; matmul term magnitude ~2e-4 vs source ~1), stored bf16^T
//   GEMM3:  loss = sqrt(||W_beta @ primary||^2) -- single-pass bf16 (norm over
//            16M elements averages out the 2^-9 rounding noise)
// mma.sync.m16n8k16 bf16 (sm_80 base ISA; tcgen05 not encodable at compute_103).
// R6 reorder regressed -> reverted to R5 loop ordering everywhere.
// ---------------------------------------------------------------------------

#define PMAX 4096
__device__ float          g_Wm  [(size_t)PMAX * PMAX];  // W_matrix fp32 (GEMM2 A)
__device__ __nv_bfloat16  g_Ttb [(size_t)PMAX * PMAX];  // target^T bf16 (GEMM2 B)
__device__ __nv_bfloat16  g_PrTb[(size_t)PMAX * PMAX];  // primary^T bf16 (GEMM3 B)
__device__ float  g_W[PMAX];
__device__ double g_s;
__device__ double g_ss;

__device__ __forceinline__ uint32_t smem_u32(const void* p) {
    uint32_t a;
    asm("{ .reg .u64 t; cvta.to.shared.u64 t, %1; cvt.u32.u64 %0, t; }"
        : "=r"(a) : "l"(p));
    return a;
}

__device__ __forceinline__ void ldsm4(uint32_t* r, uint32_t addr) {
    asm volatile("ldmatrix.sync.aligned.m8n8.x4.shared.b16 {%0,%1,%2,%3}, [%4];"
        : "=r"(r[0]), "=r"(r[1]), "=r"(r[2]), "=r"(r[3]) : "r"(addr));
}

__device__ __forceinline__ void mma_bf16(float* c, const uint32_t* a,
                                         const uint32_t* b) {
    asm volatile(
        "mma.sync.aligned.m16n8k16.row.col.f32.bf16.bf16.f32 "
        "{%0,%1,%2,%3}, {%4,%5,%6,%7}, {%8,%9}, {%0,%1,%2,%3};"
        : "+f"(c[0]), "+f"(c[1]), "+f"(c[2]), "+f"(c[3])
        : "r"(a[0]), "r"(a[1]), "r"(a[2]), "r"(a[3]), "r"(b[0]), "r"(b[1]));
}

__device__ __forceinline__ void split2(float x, float y, uint32_t& h, uint32_t& l) {
    __nv_bfloat162 hp = __floats2bfloat162_rn(x, y);
    float rx = x - __low2float(hp);
    float ry = y - __high2float(hp);
    __nv_bfloat162 lp = __floats2bfloat162_rn(rx, ry);
    h = *reinterpret_cast<uint32_t*>(&hp);
    l = *reinterpret_cast<uint32_t*>(&lp);
}

__device__ __forceinline__ uint32_t cvt2(float x, float y) {
    __nv_bfloat162 hp = __floats2bfloat162_rn(x, y);
    return *reinterpret_cast<uint32_t*>(&hp);
}

#define STS64(addr, r0, r1) \
    asm volatile("st.shared.v2.b32 [%0], {%1,%2};" \
        :: "r"(addr), "r"(r0), "r"(r1) : "memory")
#define STS128(addr, r0, r1, r2, r3) \
    asm volatile("st.shared.v4.b32 [%0], {%1,%2,%3,%4};" \
        :: "r"(addr), "r"(r0), "r"(r1), "r"(r2), "r"(r3) : "memory")

// ---------------- small kernels ------------------------------------------
__global__ void init_kernel() { g_s = 0.0; g_ss = 0.0; }

__device__ __forceinline__ float blockReduceSum(float v) {
    __shared__ float sh[32];
    int lane = threadIdx.x & 31, wid = threadIdx.x >> 5;
#pragma unroll
    for (int o = 16; o; o >>= 1) v += __shfl_down_sync(0xffffffffu, v, o);
    if (lane == 0) sh[wid] = v;
    __syncthreads();
    int nw = (blockDim.x + 31) >> 5;
    v = (threadIdx.x < nw) ? sh[threadIdx.x] : 0.0f;
    if (wid == 0)
#pragma unroll
        for (int o = 16; o; o >>= 1) v += __shfl_down_sync(0xffffffffu, v, o);
    return v;
}

__global__ void sumsq_kernel(const float* __restrict__ X, size_t n) {
    float local = 0.0f;
    for (size_t i = (size_t)blockIdx.x * blockDim.x + threadIdx.x; i < n;
         i += (size_t)gridDim.x * blockDim.x) {
        float v = X[i];
        local += v * v;
    }
    float b = blockReduceSum(local);
    if (threadIdx.x == 0) atomicAdd(&g_s, (double)b);
}

__global__ void rowsum_kernel(const float* __restrict__ Wb, int P) {
    const float* r = Wb + (size_t)blockIdx.x * P;
    float local = 0.0f;
    for (int j = threadIdx.x; j < P; j += blockDim.x) local += r[j];
    float b = blockReduceSum(local);
    if (threadIdx.x == 0) g_W[blockIdx.x] = b;
}

// fp32 in -> bf16 transposed out
__global__ void transpose_bf16_kernel(const float* __restrict__ in,
                                      __nv_bfloat16* __restrict__ out, int P) {
    __shared__ float tile[32][33];
    int tx = threadIdx.x, ty = threadIdx.y;
    int x = blockIdx.x * 32 + tx;
    int y0 = blockIdx.y * 32;
#pragma unroll
    for (int j = 0; j < 32; j += 8)
        tile[ty + j][tx] = in[(size_t)(y0 + ty + j) * P + x];
    __syncthreads();
    int xo = blockIdx.y * 32 + tx;
    int yo0 = blockIdx.x * 32;
#pragma unroll
    for (int j = 0; j < 32; j += 8)
        out[(size_t)(yo0 + ty + j) * P + xo] = __float2bfloat16(tile[tx][ty + j]);
}

__global__ void finalize_kernel(float* __restrict__ out) {
    out[0] = (float)sqrt(g_ss);
}

// ---------------- GEMM common geometry ------------------------------------
// Block 128x128, BK=32, 256 threads = 8 warps 4(M)x2(N); warp tile 32x64.
#define BM 128
#define BN 128
#define BK 32
#define ROWB 80
#define TILEB (128 * ROWB)      // 10240 per bf16 plane

// ================= GEMM1: 3-pass (R5 exact loop) ===========================
#define STAGEB3 (4 * TILEB)     // Ahi|Alo|Bhi|Blo
#define SMEM_SZ3 (2 * STAGEB3)  // 81920

__global__ __launch_bounds__(256, 1) void gemm_3p_scale(
    const float* __restrict__ A, const float* __restrict__ B,
    float* __restrict__ O0, float* __restrict__ O1, int P)
{
    extern __shared__ char smraw[];
    const uint32_t sb = smem_u32(smraw);

    const int tid = threadIdx.x, lane = tid & 31, wid = tid >> 5;
    const int wm = wid >> 1, wn = wid & 1;
    const int bx = blockIdx.x, by = blockIdx.y;

    const float* Ab = A + (size_t)(by * BM) * P;
    const float* Bb = B + (size_t)(bx * BN) * P;
    const int iters = P / BK;

    float acc[2][8][4];
#pragma unroll
    for (int mt = 0; mt < 2; mt++)
#pragma unroll
        for (int nt = 0; nt < 8; nt++)
#pragma unroll
            for (int i = 0; i < 4; i++) acc[mt][nt][i] = 0.0f;

    const int lrow = tid >> 3;
    const int lkg  = tid & 7;
    const int a_row  = wm * 32 + (lane & 15);
    const int a_koff = (lane >> 4) << 3;
    const int b_n    = wn * 64 + ((lane >> 4) << 3) + (lane & 7);
    const int b_koff = ((lane >> 3) & 1) << 3;

    float4 pa[4], pb[4];
#pragma unroll
    for (int i = 0; i < 4; i++) {
        pa[i] = *(const float4*)(Ab + (size_t)(lrow + 32 * i) * P + lkg * 4);
        pb[i] = *(const float4*)(Bb + (size_t)(lrow + 32 * i) * P + lkg * 4);
    }
    {
        const uint32_t st = sb;
#pragma unroll
        for (int i = 0; i < 4; i++) {
            uint32_t off = (uint32_t)((lrow + 32 * i) * ROWB + lkg * 8);
            uint32_t h0, l0, h1, l1;
            split2(pa[i].x, pa[i].y, h0, l0);
            split2(pa[i].z, pa[i].w, h1, l1);
            STS64(st + off, h0, h1);
            STS64(st + TILEB + off, l0, l1);
            split2(pb[i].x, pb[i].y, h0, l0);
            split2(pb[i].z, pb[i].w, h1, l1);
            STS64(st + 2 * TILEB + off, h0, h1);
            STS64(st + 3 * TILEB + off, l0, l1);
        }
    }
    __syncthreads();

    for (int t = 0; t < iters; ++t) {
        const uint32_t stage = sb + (uint32_t)((t & 1) * STAGEB3);
        if (t + 1 < iters) {
            const int k0 = (t + 1) * BK;
#pragma unroll
            for (int i = 0; i < 4; i++) {
                pa[i] = *(const float4*)(Ab + (size_t)(lrow + 32 * i) * P + k0 + lkg * 4);
                pb[i] = *(const float4*)(Bb + (size_t)(lrow + 32 * i) * P + k0 + lkg * 4);
            }
        }
#pragma unroll
        for (int ch = 0; ch < 2; ch++) {
            uint32_t Ah[2][4], Al[2][4], Bh[8][2], Bl[8][2];
#pragma unroll
            for (int mt = 0; mt < 2; mt++) {
                uint32_t addr = stage +
                    (uint32_t)((a_row + mt * 16) * ROWB + (ch * 16 + a_koff) * 2);
                ldsm4(Ah[mt], addr);
                ldsm4(Al[mt], addr + TILEB);
            }
#pragma unroll
            for (int q = 0; q < 4; q++) {
                uint32_t addr = stage + 2 * TILEB +
                    (uint32_t)((b_n + q * 16) * ROWB + (ch * 16 + b_koff) * 2);
                uint32_t r[4];
                ldsm4(r, addr);
                Bh[q * 2][0] = r[0]; Bh[q * 2][1] = r[1];
                Bh[q * 2 + 1][0] = r[2]; Bh[q * 2 + 1][1] = r[3];
                ldsm4(r, addr + TILEB);
                Bl[q * 2][0] = r[0]; Bl[q * 2][1] = r[1];
                Bl[q * 2 + 1][0] = r[2]; Bl[q * 2 + 1][1] = r[3];
            }
#pragma unroll
            for (int mt = 0; mt < 2; mt++)
#pragma unroll
                for (int nt = 0; nt < 8; nt++) {
                    mma_bf16(acc[mt][nt], Ah[mt], Bh[nt]);
                    mma_bf16(acc[mt][nt], Ah[mt], Bl[nt]);
                    mma_bf16(acc[mt][nt], Al[mt], Bh[nt]);
                }
        }
        if (t + 1 < iters) {
            const uint32_t st = sb + (uint32_t)(((t + 1) & 1) * STAGEB3);
#pragma unroll
            for (int i = 0; i < 4; i++) {
                uint32_t off = (uint32_t)((lrow + 32 * i) * ROWB + lkg * 8);
                uint32_t h0, l0, h1, l1;
                split2(pa[i].x, pa[i].y, h0, l0);
                split2(pa[i].z, pa[i].w, h1, l1);
                STS64(st + off, h0, h1);
                STS64(st + TILEB + off, l0, l1);
                split2(pb[i].x, pb[i].y, h0, l0);
                split2(pb[i].z, pb[i].w, h1, l1);
                STS64(st + 2 * TILEB + off, h0, h1);
                STS64(st + 3 * TILEB + off, l0, l1);
            }
        }
        __syncthreads();
    }

    // epilogue: scale rows, store fp32 Wm + d_out copy
    float* smC = (float*)smraw;   // [128][129]
#pragma unroll
    for (int mt = 0; mt < 2; mt++)
#pragma unroll
        for (int nt = 0; nt < 8; nt++) {
            int r0 = wm * 32 + mt * 16 + (lane >> 2);
            int c0 = wn * 64 + nt * 8 + (lane & 3) * 2;
            smC[r0 * 129 + c0]           = acc[mt][nt][0];
            smC[r0 * 129 + c0 + 1]       = acc[mt][nt][1];
            smC[(r0 + 8) * 129 + c0]     = acc[mt][nt][2];
            smC[(r0 + 8) * 129 + c0 + 1] = acc[mt][nt][3];
        }
    __syncthreads();

    const double s = g_s;
    for (int it = 0; it < 16; it++) {
        int f = it * 256 + tid;
        int row = f >> 5, c4 = (f & 31) * 4;
        double w = (double)g_W[by * BM + row];
        double w2 = w * w;
        float sc = (float)(w2 / (s * w2 + 1.0));
        float4 v;
        v.x = smC[row * 129 + c4] * sc;
        v.y = smC[row * 129 + c4 + 1] * sc;
        v.z = smC[row * 129 + c4 + 2] * sc;
        v.w = smC[row * 129 + c4 + 3] * sc;
        size_t gi = (size_t)(by * BM + row) * P + bx * BN + c4;
        *(float4*)(O0 + gi) = v;
        if (O1) {
            O1[gi] = v.x; O1[gi + 1] = v.y; O1[gi + 2] = v.z; O1[gi + 3] = v.w;
        }
    }
}

// ================= single-pass bf16 GEMM (GEMM2 / GEMM3) ===================
// A fp32 (converted to bf16 hi on the fly), B already bf16 in gmem.
// MODE 2: D - aux -> store bf16 TRANSPOSED into O0
// MODE 3: g_ss += sum(D^2)
#define STAGEB1 (2 * TILEB)     // Ah | Bh
#define SMEM_SZ1 66048          // epilogue [128][129] fp32 overlay dominates

template <int MODE>
__global__ __launch_bounds__(256, 1) void gemm_1p(
    const float* __restrict__ A, const __nv_bfloat16* __restrict__ B,
    const float* __restrict__ aux, __nv_bfloat16* __restrict__ O0, int P)
{
    extern __shared__ char smraw[];
    const uint32_t sb = smem_u32(smraw);

    const int tid = threadIdx.x, lane = tid & 31, wid = tid >> 5;
    const int wm = wid >> 1, wn = wid & 1;
    const int bx = blockIdx.x, by = blockIdx.y;

    const float* Ab = A + (size_t)(by * BM) * P;
    const __nv_bfloat16* Bb = B + (size_t)(bx * BN) * P;
    const int iters = P / BK;

    float acc[2][8][4];
#pragma unroll
    for (int mt = 0; mt < 2; mt++)
#pragma unroll
        for (int nt = 0; nt < 8; nt++)
#pragma unroll
            for (int i = 0; i < 4; i++) acc[mt][nt][i] = 0.0f;

    const int lrow = tid >> 3;       // A rows: +32*i
    const int lkg  = tid & 7;
    const int brow = tid >> 2;       // B rows (bf16, 4x16B chunks/row): +64*i
    const int bkg  = tid & 3;
    const int a_row  = wm * 32 + (lane & 15);
    const int a_koff = (lane >> 4) << 3;
    const int b_n    = wn * 64 + ((lane >> 4) << 3) + (lane & 7);
    const int b_koff = ((lane >> 3) & 1) << 3;

    float4 pa[4];
    uint4  pb[2];
#pragma unroll
    for (int i = 0; i < 4; i++)
        pa[i] = *(const float4*)(Ab + (size_t)(lrow + 32 * i) * P + lkg * 4);
#pragma unroll
    for (int i = 0; i < 2; i++)
        pb[i] = *(const uint4*)(Bb + (size_t)(brow + 64 * i) * P + bkg * 8);
    {
        const uint32_t st = sb;
#pragma unroll
        for (int i = 0; i < 4; i++) {
            uint32_t off = (uint32_t)((lrow + 32 * i) * ROWB + lkg * 8);
            STS64(st + off, cvt2(pa[i].x, pa[i].y), cvt2(pa[i].z, pa[i].w));
        }
#pragma unroll
        for (int i = 0; i < 2; i++) {
            uint32_t off = (uint32_t)((brow + 64 * i) * ROWB + bkg * 16);
            STS128(st + TILEB + off, pb[i].x, pb[i].y, pb[i].z, pb[i].w);
        }
    }
    __syncthreads();

    for (int t = 0; t < iters; ++t) {
        const uint32_t stage = sb + (uint32_t)((t & 1) * STAGEB1);
        if (t + 1 < iters) {
            const int k0 = (t + 1) * BK;
#pragma unroll
            for (int i = 0; i < 4; i++)
                pa[i] = *(const float4*)(Ab + (size_t)(lrow + 32 * i) * P + k0 + lkg * 4);
#pragma unroll
            for (int i = 0; i < 2; i++)
                pb[i] = *(const uint4*)(Bb + (size_t)(brow + 64 * i) * P + k0 + bkg * 8);
        }
#pragma unroll
        for (int ch = 0; ch < 2; ch++) {
            uint32_t Ah[2][4], Bh[8][2];
#pragma unroll
            for (int mt = 0; mt < 2; mt++) {
                uint32_t addr = stage +
                    (uint32_t)((a_row + mt * 16) * ROWB + (ch * 16 + a_koff) * 2);
                ldsm4(Ah[mt], addr);
            }
#pragma unroll
            for (int q = 0; q < 4; q++) {
                uint32_t addr = stage + TILEB +
                    (uint32_t)((b_n + q * 16) * ROWB + (ch * 16 + b_koff) * 2);
                uint32_t r[4];
                ldsm4(r, addr);
                Bh[q * 2][0] = r[0]; Bh[q * 2][1] = r[1];
                Bh[q * 2 + 1][0] = r[2]; Bh[q * 2 + 1][1] = r[3];
            }
#pragma unroll
            for (int mt = 0; mt < 2; mt++)
#pragma unroll
                for (int nt = 0; nt < 8; nt++)
                    mma_bf16(acc[mt][nt], Ah[mt], Bh[nt]);
        }
        if (t + 1 < iters) {
            const uint32_t st = sb + (uint32_t)(((t + 1) & 1) * STAGEB1);
#pragma unroll
            for (int i = 0; i < 4; i++) {
                uint32_t off = (uint32_t)((lrow + 32 * i) * ROWB + lkg * 8);
                STS64(st + off, cvt2(pa[i].x, pa[i].y), cvt2(pa[i].z, pa[i].w));
            }
#pragma unroll
            for (int i = 0; i < 2; i++) {
                uint32_t off = (uint32_t)((brow + 64 * i) * ROWB + bkg * 16);
                STS128(st + TILEB + off, pb[i].x, pb[i].y, pb[i].z, pb[i].w);
            }
        }
        __syncthreads();
    }

    if (MODE == 3) {
        float local = 0.0f;
#pragma unroll
        for (int mt = 0; mt < 2; mt++)
#pragma unroll
            for (int nt = 0; nt < 8; nt++)
#pragma unroll
                for (int i = 0; i < 4; i++)
                    local += acc[mt][nt][i] * acc[mt][nt][i];
        float bsum = blockReduceSum(local);
        if (tid == 0) atomicAdd(&g_ss, (double)bsum);
        return;
    }

    // MODE 2: subtract aux, store transposed bf16
    float* smC = (float*)smraw;   // [128][129]
#pragma unroll
    for (int mt = 0; mt < 2; mt++)
#pragma unroll
        for (int nt = 0; nt < 8; nt++) {
            int r0 = wm * 32 + mt * 16 + (lane >> 2);
            int c0 = wn * 64 + nt * 8 + (lane & 3) * 2;
            smC[r0 * 129 + c0]           = acc[mt][nt][0];
            smC[r0 * 129 + c0 + 1]       = acc[mt][nt][1];
            smC[(r0 + 8) * 129 + c0]     = acc[mt][nt][2];
            smC[(r0 + 8) * 129 + c0 + 1] = acc[mt][nt][3];
        }
    __syncthreads();

    for (int it = 0; it < 16; it++) {
        int f = it * 256 + tid;
        int row = f >> 5, c4 = (f & 31) * 4;
        float4 sv = *(const float4*)(aux + (size_t)(by * BM + row) * P + bx * BN + c4);
        smC[row * 129 + c4]     -= sv.x;
        smC[row * 129 + c4 + 1] -= sv.y;
        smC[row * 129 + c4 + 2] -= sv.z;
        smC[row * 129 + c4 + 3] -= sv.w;
    }
    __syncthreads();
    for (int it = 0; it < 16; it++) {
        int f = it * 256 + tid;
        int n = f >> 5, m4 = (f & 31) * 4;
        uint2 pk;
        pk.x = cvt2(smC[(m4 + 0) * 129 + n], smC[(m4 + 1) * 129 + n]);
        pk.y = cvt2(smC[(m4 + 2) * 129 + n], smC[(m4 + 3) * 129 + n]);
        *(uint2*)(O0 + (size_t)(bx * BN + n) * P + by * BM + m4) = pk;
    }
}

// ---------------- launch ---------------------------------------------------
extern "C" void kernel_launch(void* const* d_in, const int* in_sizes, int n_in,
                              void* d_out, int out_size)
{
    const float* target = (const float*)d_in[0];
    const float* source = (const float*)d_in[1];
    const float* Wb     = (const float*)d_in[2];
    float* out = (float*)d_out;

    int P = (int)(sqrt((double)in_sizes[0]) + 0.5);
    size_t pp = (size_t)P * P;

    bool has_matrix = (size_t)out_size >= pp;
    bool has_loss   = ((size_t)out_size != pp);
    float* outW = has_matrix ? (out + (out_size - (int)pp)) : nullptr;

    float* wm = nullptr;           cudaGetSymbolAddress((void**)&wm,  g_Wm);
    __nv_bfloat16* ttb = nullptr;  cudaGetSymbolAddress((void**)&ttb, g_Ttb);
    __nv_bfloat16* prb = nullptr;  cudaGetSymbolAddress((void**)&prb, g_PrTb);

    cudaFuncSetAttribute(gemm_3p_scale, cudaFuncAttributeMaxDynamicSharedMemorySize, SMEM_SZ3);
    cudaFuncSetAttribute(gemm_1p<2>, cudaFuncAttributeMaxDynamicSharedMemorySize, SMEM_SZ1);
    cudaFuncSetAttribute(gemm_1p<3>, cudaFuncAttributeMaxDynamicSharedMemorySize, SMEM_SZ1);

    init_kernel<<<1, 1>>>();
    sumsq_kernel<<<2048, 256>>>(target, pp);
    rowsum_kernel<<<P, 256>>>(Wb, P);
    transpose_bf16_kernel<<<dim3(P / 32, P / 32), dim3(32, 8)>>>(target, ttb, P);

    dim3 grid(P / BN, P / BM);
    // Wm = scale .* (source @ target^T)   [3-pass, full accuracy]
    gemm_3p_scale<<<grid, 256, SMEM_SZ3>>>(source, target, wm, outW, P);
    // primary^T (bf16) = (Wm @ target - source)^T   [1-pass]
    gemm_1p<2><<<grid, 256, SMEM_SZ1>>>(wm, ttb, source, prb, P);
    // ss += ||W_beta @ primary||^2                   [1-pass]
    gemm_1p<3><<<grid, 256, SMEM_SZ1>>>(Wb, prb, nullptr, nullptr, P);

    if (has_loss) finalize_kernel<<<1, 1>>>(out);
}

// round 8
// speedup vs baseline: 1.8568x; 1.1537x over previous
#include <cuda_runtime.h>
#include <cuda_bf16.h>
#include <math.h>
#include <stdint.h>

// ---------------------------------------------------------------------------
//   s     = sum(target^2);  W[i] = rowsum(W_beta);  scale_i = W^2/(s W^2+1)
//   GEMM1: Wm = scale .* (source @ target^T)   bf16x3 (3-pass), fp32-out
//   GEMM2: primary^T = (Wm @ target - source)^T  1-pass bf16 (loss path only)
//   GEMM3: loss = sqrt(||W_beta @ primary||^2)   1-pass bf16
// R8: all operands pre-converted to bf16 hi/lo planes in gmem; GEMM mainloops
// use cp.async.cg multi-stage pipelines (3 / 4 stages), no in-loop convert.
// ---------------------------------------------------------------------------

#define PMAX 4096
#define NELEM ((size_t)PMAX * PMAX)
__device__ __nv_bfloat16 g_Shi[NELEM], g_Slo[NELEM];   // source hi/lo
__device__ __nv_bfloat16 g_Thi[NELEM], g_Tlo[NELEM];   // target hi/lo
__device__ __nv_bfloat16 g_Wbh[NELEM];                 // W_beta hi
__device__ __nv_bfloat16 g_Ttb[NELEM];                 // target^T
__device__ __nv_bfloat16 g_Wmh[NELEM];                 // Wm hi (GEMM1 out)
__device__ __nv_bfloat16 g_PrTb[NELEM];                // primary^T
__device__ float  g_W[PMAX];
__device__ double g_s;
__device__ double g_ss;

__device__ __forceinline__ uint32_t smem_u32(const void* p) {
    uint32_t a;
    asm("{ .reg .u64 t; cvta.to.shared.u64 t, %1; cvt.u32.u64 %0, t; }"
        : "=r"(a) : "l"(p));
    return a;
}

__device__ __forceinline__ void ldsm4(uint32_t* r, uint32_t addr) {
    asm volatile("ldmatrix.sync.aligned.m8n8.x4.shared.b16 {%0,%1,%2,%3}, [%4];"
        : "=r"(r[0]), "=r"(r[1]), "=r"(r[2]), "=r"(r[3]) : "r"(addr));
}

__device__ __forceinline__ void mma_bf16(float* c, const uint32_t* a,
                                         const uint32_t* b) {
    asm volatile(
        "mma.sync.aligned.m16n8k16.row.col.f32.bf16.bf16.f32 "
        "{%0,%1,%2,%3}, {%4,%5,%6,%7}, {%8,%9}, {%0,%1,%2,%3};"
        : "+f"(c[0]), "+f"(c[1]), "+f"(c[2]), "+f"(c[3])
        : "r"(a[0]), "r"(a[1]), "r"(a[2]), "r"(a[3]), "r"(b[0]), "r"(b[1]));
}

__device__ __forceinline__ uint32_t cvt2(float x, float y) {
    __nv_bfloat162 hp = __floats2bfloat162_rn(x, y);
    return *reinterpret_cast<uint32_t*>(&hp);
}

#define CP16(sm, gp) \
    asm volatile("cp.async.cg.shared.global [%0], [%1], 16;" \
        :: "r"(sm), "l"(gp) : "memory")
#define CP_COMMIT() asm volatile("cp.async.commit_group;" ::: "memory")
#define CP_WAIT(N)  asm volatile("cp.async.wait_group %0;" :: "n"(N) : "memory")

// ---------------- small kernels ------------------------------------------
__global__ void init_kernel() { g_s = 0.0; g_ss = 0.0; }

__device__ __forceinline__ float blockReduceSum(float v) {
    __shared__ float sh[32];
    int lane = threadIdx.x & 31, wid = threadIdx.x >> 5;
#pragma unroll
    for (int o = 16; o; o >>= 1) v += __shfl_down_sync(0xffffffffu, v, o);
    if (lane == 0) sh[wid] = v;
    __syncthreads();
    int nw = (blockDim.x + 31) >> 5;
    v = (threadIdx.x < nw) ? sh[threadIdx.x] : 0.0f;
    if (wid == 0)
#pragma unroll
        for (int o = 16; o; o >>= 1) v += __shfl_down_sync(0xffffffffu, v, o);
    return v;
}

// fp32 -> bf16 hi/lo planes; optional fused sum(x^2)
template <bool SUMSQ>
__global__ void split_kernel(const float* __restrict__ in,
                             __nv_bfloat16* __restrict__ hi,
                             __nv_bfloat16* __restrict__ lo, size_t n4) {
    float local = 0.0f;
    for (size_t i = (size_t)blockIdx.x * blockDim.x + threadIdx.x; i < n4;
         i += (size_t)gridDim.x * blockDim.x) {
        float4 v = ((const float4*)in)[i];
        __nv_bfloat162 h0 = __floats2bfloat162_rn(v.x, v.y);
        __nv_bfloat162 h1 = __floats2bfloat162_rn(v.z, v.w);
        __nv_bfloat162 l0 = __floats2bfloat162_rn(v.x - __low2float(h0),
                                                  v.y - __high2float(h0));
        __nv_bfloat162 l1 = __floats2bfloat162_rn(v.z - __low2float(h1),
                                                  v.w - __high2float(h1));
        uint2 hp = make_uint2(*(uint32_t*)&h0, *(uint32_t*)&h1);
        uint2 lp = make_uint2(*(uint32_t*)&l0, *(uint32_t*)&l1);
        ((uint2*)hi)[i] = hp;
        ((uint2*)lo)[i] = lp;
        if (SUMSQ) local += v.x * v.x + v.y * v.y + v.z * v.z + v.w * v.w;
    }
    if (SUMSQ) {
        float b = blockReduceSum(local);
        if (threadIdx.x == 0) atomicAdd(&g_s, (double)b);
    }
}

// W_beta -> bf16 hi plane + fused row sums (one block per row)
__global__ void wb_convert_kernel(const float* __restrict__ Wb,
                                  __nv_bfloat16* __restrict__ hi, int P) {
    const int row = blockIdx.x;
    const float4* r4 = (const float4*)(Wb + (size_t)row * P);
    uint2* h4 = (uint2*)(hi + (size_t)row * P);
    float local = 0.0f;
    for (int j = threadIdx.x; j < P / 4; j += blockDim.x) {
        float4 v = r4[j];
        __nv_bfloat162 h0 = __floats2bfloat162_rn(v.x, v.y);
        __nv_bfloat162 h1 = __floats2bfloat162_rn(v.z, v.w);
        h4[j] = make_uint2(*(uint32_t*)&h0, *(uint32_t*)&h1);
        local += v.x + v.y + v.z + v.w;
    }
    float b = blockReduceSum(local);
    if (threadIdx.x == 0) g_W[row] = b;
}

// fp32 in -> bf16 transposed out
__global__ void transpose_bf16_kernel(const float* __restrict__ in,
                                      __nv_bfloat16* __restrict__ out, int P) {
    __shared__ float tile[32][33];
    int tx = threadIdx.x, ty = threadIdx.y;
    int x = blockIdx.x * 32 + tx;
    int y0 = blockIdx.y * 32;
#pragma unroll
    for (int j = 0; j < 32; j += 8)
        tile[ty + j][tx] = in[(size_t)(y0 + ty + j) * P + x];
    __syncthreads();
    int xo = blockIdx.y * 32 + tx;
    int yo0 = blockIdx.x * 32;
#pragma unroll
    for (int j = 0; j < 32; j += 8)
        out[(size_t)(yo0 + ty + j) * P + xo] = __float2bfloat16(tile[tx][ty + j]);
}

__global__ void finalize_kernel(float* __restrict__ out) {
    out[0] = (float)sqrt(g_ss);
}

// ---------------- GEMM geometry -------------------------------------------
#define BM 128
#define BN 128
#define BK 32
#define ROWB 80                 // 64B data + 16B pad (16B-aligned rows)
#define TILEB (128 * ROWB)      // 10240 per plane per stage

// ================= GEMM1: 3-pass, 4 planes, 3-stage cp.async ===============
#define ST3 3
#define STAGEB3 (4 * TILEB)             // Ah|Al|Bh|Bl = 40960
#define SMEM_SZ3 (ST3 * STAGEB3)        // 122880 (epilogue overlays)

__global__ __launch_bounds__(256, 1) void gemm_3p_scale(
    const __nv_bfloat16* __restrict__ Ah_g, const __nv_bfloat16* __restrict__ Al_g,
    const __nv_bfloat16* __restrict__ Bh_g, const __nv_bfloat16* __restrict__ Bl_g,
    float* __restrict__ O1, __nv_bfloat16* __restrict__ Ob, int P)
{
    extern __shared__ char smraw[];
    const uint32_t sb = smem_u32(smraw);

    const int tid = threadIdx.x, lane = tid & 31, wid = tid >> 5;
    const int wm = wid >> 1, wn = wid & 1;
    const int bx = blockIdx.x, by = blockIdx.y;

    const __nv_bfloat16* At_h = Ah_g + (size_t)(by * BM) * P;
    const __nv_bfloat16* At_l = Al_g + (size_t)(by * BM) * P;
    const __nv_bfloat16* Bt_h = Bh_g + (size_t)(bx * BN) * P;
    const __nv_bfloat16* Bt_l = Bl_g + (size_t)(bx * BN) * P;
    const int iters = P / BK;

    const int crow = tid >> 1;           // cp.async: 2 slots/thread/plane
    const int cch  = (tid & 1) * 2;      // chunks {0,1} or {2,3}
    const int a_row  = wm * 32 + (lane & 15);
    const int a_koff = (lane >> 4) << 3;
    const int b_n    = wn * 64 + ((lane >> 4) << 3) + (lane & 7);
    const int b_koff = ((lane >> 3) & 1) << 3;

    float acc[2][8][4];
#pragma unroll
    for (int mt = 0; mt < 2; mt++)
#pragma unroll
        for (int nt = 0; nt < 8; nt++)
#pragma unroll
            for (int i = 0; i < 4; i++) acc[mt][nt][i] = 0.0f;

    auto issue = [&](int s, int k0) {
        const uint32_t st = sb + (uint32_t)(s * STAGEB3);
#pragma unroll
        for (int c = 0; c < 2; c++) {
            uint32_t off = (uint32_t)(crow * ROWB + (cch + c) * 16);
            size_t go = (size_t)crow * P + k0 + (cch + c) * 8;
            CP16(st + off,             At_h + go);
            CP16(st + TILEB + off,     At_l + go);
            CP16(st + 2 * TILEB + off, Bt_h + go);
            CP16(st + 3 * TILEB + off, Bt_l + go);
        }
    };

#pragma unroll
    for (int s = 0; s < ST3 - 1; s++) { issue(s, s * BK); CP_COMMIT(); }

    for (int t = 0; t < iters; ++t) {
        CP_WAIT(ST3 - 2);
        __syncthreads();
        if (t + ST3 - 1 < iters) issue((t + ST3 - 1) % ST3, (t + ST3 - 1) * BK);
        CP_COMMIT();

        const uint32_t stage = sb + (uint32_t)((t % ST3) * STAGEB3);
#pragma unroll
        for (int ch = 0; ch < 2; ch++) {
            uint32_t Ahf[2][4], Alf[2][4], Bhf[8][2], Blf[8][2];
#pragma unroll
            for (int mt = 0; mt < 2; mt++) {
                uint32_t addr = stage +
                    (uint32_t)((a_row + mt * 16) * ROWB + (ch * 16 + a_koff) * 2);
                ldsm4(Ahf[mt], addr);
                ldsm4(Alf[mt], addr + TILEB);
            }
#pragma unroll
            for (int q = 0; q < 4; q++) {
                uint32_t addr = stage + 2 * TILEB +
                    (uint32_t)((b_n + q * 16) * ROWB + (ch * 16 + b_koff) * 2);
                uint32_t r[4];
                ldsm4(r, addr);
                Bhf[q * 2][0] = r[0]; Bhf[q * 2][1] = r[1];
                Bhf[q * 2 + 1][0] = r[2]; Bhf[q * 2 + 1][1] = r[3];
                ldsm4(r, addr + TILEB);
                Blf[q * 2][0] = r[0]; Blf[q * 2][1] = r[1];
                Blf[q * 2 + 1][0] = r[2]; Blf[q * 2 + 1][1] = r[3];
            }
#pragma unroll
            for (int mt = 0; mt < 2; mt++)
#pragma unroll
                for (int nt = 0; nt < 8; nt++) {
                    mma_bf16(acc[mt][nt], Ahf[mt], Bhf[nt]);
                    mma_bf16(acc[mt][nt], Ahf[mt], Blf[nt]);
                    mma_bf16(acc[mt][nt], Alf[mt], Bhf[nt]);
                }
        }
    }
    CP_WAIT(0);
    __syncthreads();

    // epilogue: scale rows; emit fp32 to O1 (d_out, maybe unaligned) + bf16 Wm hi
    float* smC = (float*)smraw;   // [128][129]
#pragma unroll
    for (int mt = 0; mt < 2; mt++)
#pragma unroll
        for (int nt = 0; nt < 8; nt++) {
            int r0 = wm * 32 + mt * 16 + (lane >> 2);
            int c0 = wn * 64 + nt * 8 + (lane & 3) * 2;
            smC[r0 * 129 + c0]           = acc[mt][nt][0];
            smC[r0 * 129 + c0 + 1]       = acc[mt][nt][1];
            smC[(r0 + 8) * 129 + c0]     = acc[mt][nt][2];
            smC[(r0 + 8) * 129 + c0 + 1] = acc[mt][nt][3];
        }
    __syncthreads();

    const double s = g_s;
    for (int it = 0; it < 16; it++) {
        int f = it * 256 + tid;
        int row = f >> 5, c4 = (f & 31) * 4;
        double w = (double)g_W[by * BM + row];
        double w2 = w * w;
        float sc = (float)(w2 / (s * w2 + 1.0));
        float4 v;
        v.x = smC[row * 129 + c4] * sc;
        v.y = smC[row * 129 + c4 + 1] * sc;
        v.z = smC[row * 129 + c4 + 2] * sc;
        v.w = smC[row * 129 + c4 + 3] * sc;
        size_t gi = (size_t)(by * BM + row) * P + bx * BN + c4;
        if (O1) {
            O1[gi] = v.x; O1[gi + 1] = v.y; O1[gi + 2] = v.z; O1[gi + 3] = v.w;
        }
        *(uint2*)(Ob + gi) = make_uint2(cvt2(v.x, v.y), cvt2(v.z, v.w));
    }
}

// ================= single-pass bf16 GEMM, 4-stage cp.async =================
#define ST1 4
#define STAGEB1 (2 * TILEB)             // Ah|Bh = 20480
#define SMEM_SZ1 (ST1 * STAGEB1)        // 81920 (epilogue overlays)

// MODE 2: D - aux -> bf16 transposed O0;  MODE 3: g_ss += sum(D^2)
template <int MODE>
__global__ __launch_bounds__(256, 2) void gemm_1p(
    const __nv_bfloat16* __restrict__ A, const __nv_bfloat16* __restrict__ B,
    const float* __restrict__ aux, __nv_bfloat16* __restrict__ O0, int P)
{
    extern __shared__ char smraw[];
    const uint32_t sb = smem_u32(smraw);

    const int tid = threadIdx.x, lane = tid & 31, wid = tid >> 5;
    const int wm = wid >> 1, wn = wid & 1;
    const int bx = blockIdx.x, by = blockIdx.y;

    const __nv_bfloat16* At = A + (size_t)(by * BM) * P;
    const __nv_bfloat16* Bt = B + (size_t)(bx * BN) * P;
    const int iters = P / BK;

    const int crow = tid >> 1;
    const int cch  = (tid & 1) * 2;
    const int a_row  = wm * 32 + (lane & 15);
    const int a_koff = (lane >> 4) << 3;
    const int b_n    = wn * 64 + ((lane >> 4) << 3) + (lane & 7);
    const int b_koff = ((lane >> 3) & 1) << 3;

    float acc[2][8][4];
#pragma unroll
    for (int mt = 0; mt < 2; mt++)
#pragma unroll
        for (int nt = 0; nt < 8; nt++)
#pragma unroll
            for (int i = 0; i < 4; i++) acc[mt][nt][i] = 0.0f;

    auto issue = [&](int s, int k0) {
        const uint32_t st = sb + (uint32_t)(s * STAGEB1);
#pragma unroll
        for (int c = 0; c < 2; c++) {
            uint32_t off = (uint32_t)(crow * ROWB + (cch + c) * 16);
            size_t go = (size_t)crow * P + k0 + (cch + c) * 8;
            CP16(st + off,         At + go);
            CP16(st + TILEB + off, Bt + go);
        }
    };

#pragma unroll
    for (int s = 0; s < ST1 - 1; s++) { issue(s, s * BK); CP_COMMIT(); }

    for (int t = 0; t < iters; ++t) {
        CP_WAIT(ST1 - 2);
        __syncthreads();
        if (t + ST1 - 1 < iters) issue((t + ST1 - 1) % ST1, (t + ST1 - 1) * BK);
        CP_COMMIT();

        const uint32_t stage = sb + (uint32_t)((t % ST1) * STAGEB1);
#pragma unroll
        for (int ch = 0; ch < 2; ch++) {
            uint32_t Ahf[2][4], Bhf[8][2];
#pragma unroll
            for (int mt = 0; mt < 2; mt++) {
                uint32_t addr = stage +
                    (uint32_t)((a_row + mt * 16) * ROWB + (ch * 16 + a_koff) * 2);
                ldsm4(Ahf[mt], addr);
            }
#pragma unroll
            for (int q = 0; q < 4; q++) {
                uint32_t addr = stage + TILEB +
                    (uint32_t)((b_n + q * 16) * ROWB + (ch * 16 + b_koff) * 2);
                uint32_t r[4];
                ldsm4(r, addr);
                Bhf[q * 2][0] = r[0]; Bhf[q * 2][1] = r[1];
                Bhf[q * 2 + 1][0] = r[2]; Bhf[q * 2 + 1][1] = r[3];
            }
#pragma unroll
            for (int mt = 0; mt < 2; mt++)
#pragma unroll
                for (int nt = 0; nt < 8; nt++)
                    mma_bf16(acc[mt][nt], Ahf[mt], Bhf[nt]);
        }
    }
    CP_WAIT(0);
    __syncthreads();

    if (MODE == 3) {
        float local = 0.0f;
#pragma unroll
        for (int mt = 0; mt < 2; mt++)
#pragma unroll
            for (int nt = 0; nt < 8; nt++)
#pragma unroll
                for (int i = 0; i < 4; i++)
                    local += acc[mt][nt][i] * acc[mt][nt][i];
        float bsum = blockReduceSum(local);
        if (tid == 0) atomicAdd(&g_ss, (double)bsum);
        return;
    }

    // MODE 2: subtract aux, store transposed bf16
    float* smC = (float*)smraw;   // [128][129]
#pragma unroll
    for (int mt = 0; mt < 2; mt++)
#pragma unroll
        for (int nt = 0; nt < 8; nt++) {
            int r0 = wm * 32 + mt * 16 + (lane >> 2);
            int c0 = wn * 64 + nt * 8 + (lane & 3) * 2;
            smC[r0 * 129 + c0]           = acc[mt][nt][0];
            smC[r0 * 129 + c0 + 1]       = acc[mt][nt][1];
            smC[(r0 + 8) * 129 + c0]     = acc[mt][nt][2];
            smC[(r0 + 8) * 129 + c0 + 1] = acc[mt][nt][3];
        }
    __syncthreads();

    for (int it = 0; it < 16; it++) {
        int f = it * 256 + tid;
        int row = f >> 5, c4 = (f & 31) * 4;
        float4 sv = *(const float4*)(aux + (size_t)(by * BM + row) * P + bx * BN + c4);
        smC[row * 129 + c4]     -= sv.x;
        smC[row * 129 + c4 + 1] -= sv.y;
        smC[row * 129 + c4 + 2] -= sv.z;
        smC[row * 129 + c4 + 3] -= sv.w;
    }
    __syncthreads();
    for (int it = 0; it < 16; it++) {
        int f = it * 256 + tid;
        int n = f >> 5, m4 = (f & 31) * 4;
        uint2 pk;
        pk.x = cvt2(smC[(m4 + 0) * 129 + n], smC[(m4 + 1) * 129 + n]);
        pk.y = cvt2(smC[(m4 + 2) * 129 + n], smC[(m4 + 3) * 129 + n]);
        *(uint2*)(O0 + (size_t)(bx * BN + n) * P + by * BM + m4) = pk;
    }
}

// ---------------- launch ---------------------------------------------------
extern "C" void kernel_launch(void* const* d_in, const int* in_sizes, int n_in,
                              void* d_out, int out_size)
{
    const float* target = (const float*)d_in[0];
    const float* source = (const float*)d_in[1];
    const float* Wb     = (const float*)d_in[2];
    float* out = (float*)d_out;

    int P = (int)(sqrt((double)in_sizes[0]) + 0.5);
    size_t pp = (size_t)P * P;

    bool has_matrix = (size_t)out_size >= pp;
    bool has_loss   = ((size_t)out_size != pp);
    float* outW = has_matrix ? (out + (out_size - (int)pp)) : nullptr;

    __nv_bfloat16 *shi, *slo, *thi, *tlo, *wbh, *ttb, *wmh, *prb;
    cudaGetSymbolAddress((void**)&shi, g_Shi);
    cudaGetSymbolAddress((void**)&slo, g_Slo);
    cudaGetSymbolAddress((void**)&thi, g_Thi);
    cudaGetSymbolAddress((void**)&tlo, g_Tlo);
    cudaGetSymbolAddress((void**)&wbh, g_Wbh);
    cudaGetSymbolAddress((void**)&ttb, g_Ttb);
    cudaGetSymbolAddress((void**)&wmh, g_Wmh);
    cudaGetSymbolAddress((void**)&prb, g_PrTb);

    cudaFuncSetAttribute(gemm_3p_scale, cudaFuncAttributeMaxDynamicSharedMemorySize, SMEM_SZ3);
    cudaFuncSetAttribute(gemm_1p<2>, cudaFuncAttributeMaxDynamicSharedMemorySize, SMEM_SZ1);
    cudaFuncSetAttribute(gemm_1p<3>, cudaFuncAttributeMaxDynamicSharedMemorySize, SMEM_SZ1);

    init_kernel<<<1, 1>>>();
    split_kernel<false><<<1024, 256>>>(source, shi, slo, pp / 4);
    split_kernel<true><<<1024, 256>>>(target, thi, tlo, pp / 4);
    wb_convert_kernel<<<P, 256>>>(Wb, wbh, P);
    transpose_bf16_kernel<<<dim3(P / 32, P / 32), dim3(32, 8)>>>(target, ttb, P);

    dim3 grid(P / BN, P / BM);
    // Wm = scale .* (source @ target^T)   [3-pass]
    gemm_3p_scale<<<grid, 256, SMEM_SZ3>>>(shi, slo, thi, tlo, outW, wmh, P);
    // primary^T (bf16) = (Wm @ target - source)^T   [1-pass]
    gemm_1p<2><<<grid, 256, SMEM_SZ1>>>(wmh, ttb, source, prb, P);
    // ss += ||W_beta @ primary||^2                   [1-pass]
    gemm_1p<3><<<grid, 256, SMEM_SZ1>>>(wbh, prb, nullptr, nullptr, P);

    if (has_loss) finalize_kernel<<<1, 1>>>(out);
}

// round 9
// speedup vs baseline: 2.2172x; 1.1941x over previous
#include <cuda_runtime.h>
#include <cuda_bf16.h>
#include <cuda_fp16.h>
#include <math.h>
#include <stdint.h>

// ---------------------------------------------------------------------------
//   s     = sum(target^2);  W[i] = rowsum(W_beta);  scale_i = W^2/(s W^2+1)
//   GEMM1: Wm = scale .* (source @ target^T)   fp16x2 (A split hi/lo, B hi):
//          C = Ah*Bh + Al*Bh; dropped A*Bl term ~1.4e-4 rel (fp16 u=2^-11)
//   GEMM2: primary^T = (Wm @ target - source)^T  1-pass bf16 (loss path only)
//   GEMM3: loss = sqrt(||W_beta @ primary||^2)   1-pass bf16
// All GEMM mainloops: cp.async.cg multi-stage pipelines, pre-converted
// operand planes in gmem, mma.sync.m16n8k16 (f16 or bf16).
// ---------------------------------------------------------------------------

#define PMAX 4096
#define NELEM ((size_t)PMAX * PMAX)
__device__ __half         g_Shi[NELEM], g_Slo[NELEM];  // source fp16 hi/lo
__device__ __half         g_Thi[NELEM];                // target fp16 hi
__device__ __nv_bfloat16  g_Wbh[NELEM];                // W_beta bf16 hi
__device__ __nv_bfloat16  g_Ttb[NELEM];                // target^T bf16
__device__ __nv_bfloat16  g_Wmh[NELEM];                // Wm bf16 hi (GEMM1 out)
__device__ __nv_bfloat16  g_PrTb[NELEM];               // primary^T bf16
__device__ float  g_W[PMAX];
__device__ double g_s;
__device__ double g_ss;

__device__ __forceinline__ uint32_t smem_u32(const void* p) {
    uint32_t a;
    asm("{ .reg .u64 t; cvta.to.shared.u64 t, %1; cvt.u32.u64 %0, t; }"
        : "=r"(a) : "l"(p));
    return a;
}

__device__ __forceinline__ void ldsm4(uint32_t* r, uint32_t addr) {
    asm volatile("ldmatrix.sync.aligned.m8n8.x4.shared.b16 {%0,%1,%2,%3}, [%4];"
        : "=r"(r[0]), "=r"(r[1]), "=r"(r[2]), "=r"(r[3]) : "r"(addr));
}

__device__ __forceinline__ void mma_bf16(float* c, const uint32_t* a,
                                         const uint32_t* b) {
    asm volatile(
        "mma.sync.aligned.m16n8k16.row.col.f32.bf16.bf16.f32 "
        "{%0,%1,%2,%3}, {%4,%5,%6,%7}, {%8,%9}, {%0,%1,%2,%3};"
        : "+f"(c[0]), "+f"(c[1]), "+f"(c[2]), "+f"(c[3])
        : "r"(a[0]), "r"(a[1]), "r"(a[2]), "r"(a[3]), "r"(b[0]), "r"(b[1]));
}

__device__ __forceinline__ void mma_f16(float* c, const uint32_t* a,
                                        const uint32_t* b) {
    asm volatile(
        "mma.sync.aligned.m16n8k16.row.col.f32.f16.f16.f32 "
        "{%0,%1,%2,%3}, {%4,%5,%6,%7}, {%8,%9}, {%0,%1,%2,%3};"
        : "+f"(c[0]), "+f"(c[1]), "+f"(c[2]), "+f"(c[3])
        : "r"(a[0]), "r"(a[1]), "r"(a[2]), "r"(a[3]), "r"(b[0]), "r"(b[1]));
}

__device__ __forceinline__ uint32_t cvt2bf(float x, float y) {
    __nv_bfloat162 hp = __floats2bfloat162_rn(x, y);
    return *reinterpret_cast<uint32_t*>(&hp);
}

#define CP16(sm, gp) \
    asm volatile("cp.async.cg.shared.global [%0], [%1], 16;" \
        :: "r"(sm), "l"(gp) : "memory")
#define CP_COMMIT() asm volatile("cp.async.commit_group;" ::: "memory")
#define CP_WAIT(N)  asm volatile("cp.async.wait_group %0;" :: "n"(N) : "memory")

// ---------------- small kernels ------------------------------------------
__global__ void init_kernel() { g_s = 0.0; g_ss = 0.0; }

__device__ __forceinline__ float blockReduceSum(float v) {
    __shared__ float sh[32];
    int lane = threadIdx.x & 31, wid = threadIdx.x >> 5;
#pragma unroll
    for (int o = 16; o; o >>= 1) v += __shfl_down_sync(0xffffffffu, v, o);
    if (lane == 0) sh[wid] = v;
    __syncthreads();
    int nw = (blockDim.x + 31) >> 5;
    v = (threadIdx.x < nw) ? sh[threadIdx.x] : 0.0f;
    if (wid == 0)
#pragma unroll
        for (int o = 16; o; o >>= 1) v += __shfl_down_sync(0xffffffffu, v, o);
    return v;
}

// source -> fp16 hi/lo planes
__global__ void split_f16_kernel(const float* __restrict__ in,
                                 __half* __restrict__ hi,
                                 __half* __restrict__ lo, size_t n4) {
    for (size_t i = (size_t)blockIdx.x * blockDim.x + threadIdx.x; i < n4;
         i += (size_t)gridDim.x * blockDim.x) {
        float4 v = ((const float4*)in)[i];
        __half2 h0 = __floats2half2_rn(v.x, v.y);
        __half2 h1 = __floats2half2_rn(v.z, v.w);
        __half2 l0 = __floats2half2_rn(v.x - __low2float(h0),
                                       v.y - __high2float(h0));
        __half2 l1 = __floats2half2_rn(v.z - __low2float(h1),
                                       v.w - __high2float(h1));
        ((uint2*)hi)[i] = make_uint2(*(uint32_t*)&h0, *(uint32_t*)&h1);
        ((uint2*)lo)[i] = make_uint2(*(uint32_t*)&l0, *(uint32_t*)&l1);
    }
}

// target -> fp16 hi plane + fused sum(x^2)
__global__ void thi_sumsq_kernel(const float* __restrict__ in,
                                 __half* __restrict__ hi, size_t n4) {
    float local = 0.0f;
    for (size_t i = (size_t)blockIdx.x * blockDim.x + threadIdx.x; i < n4;
         i += (size_t)gridDim.x * blockDim.x) {
        float4 v = ((const float4*)in)[i];
        __half2 h0 = __floats2half2_rn(v.x, v.y);
        __half2 h1 = __floats2half2_rn(v.z, v.w);
        ((uint2*)hi)[i] = make_uint2(*(uint32_t*)&h0, *(uint32_t*)&h1);
        local += v.x * v.x + v.y * v.y + v.z * v.z + v.w * v.w;
    }
    float b = blockReduceSum(local);
    if (threadIdx.x == 0) atomicAdd(&g_s, (double)b);
}

// W_beta -> bf16 hi plane + fused row sums (one block per row)
__global__ void wb_convert_kernel(const float* __restrict__ Wb,
                                  __nv_bfloat16* __restrict__ hi, int P) {
    const int row = blockIdx.x;
    const float4* r4 = (const float4*)(Wb + (size_t)row * P);
    uint2* h4 = (uint2*)(hi + (size_t)row * P);
    float local = 0.0f;
    for (int j = threadIdx.x; j < P / 4; j += blockDim.x) {
        float4 v = r4[j];
        __nv_bfloat162 h0 = __floats2bfloat162_rn(v.x, v.y);
        __nv_bfloat162 h1 = __floats2bfloat162_rn(v.z, v.w);
        h4[j] = make_uint2(*(uint32_t*)&h0, *(uint32_t*)&h1);
        local += v.x + v.y + v.z + v.w;
    }
    float b = blockReduceSum(local);
    if (threadIdx.x == 0) g_W[row] = b;
}

// fp32 in -> bf16 transposed out
__global__ void transpose_bf16_kernel(const float* __restrict__ in,
                                      __nv_bfloat16* __restrict__ out, int P) {
    __shared__ float tile[32][33];
    int tx = threadIdx.x, ty = threadIdx.y;
    int x = blockIdx.x * 32 + tx;
    int y0 = blockIdx.y * 32;
#pragma unroll
    for (int j = 0; j < 32; j += 8)
        tile[ty + j][tx] = in[(size_t)(y0 + ty + j) * P + x];
    __syncthreads();
    int xo = blockIdx.y * 32 + tx;
    int yo0 = blockIdx.x * 32;
#pragma unroll
    for (int j = 0; j < 32; j += 8)
        out[(size_t)(yo0 + ty + j) * P + xo] = __float2bfloat16(tile[tx][ty + j]);
}

__global__ void finalize_kernel(float* __restrict__ out) {
    out[0] = (float)sqrt(g_ss);
}

// ---------------- GEMM geometry -------------------------------------------
#define BM 128
#define BN 128
#define BK 32
#define ROWB 80
#define TILEB (128 * ROWB)      // 10240 per plane per stage

// ================= GEMM1: fp16 2-pass, 3 planes, 3-stage cp.async ==========
#define ST3 3
#define STAGEB3 (3 * TILEB)             // Ah|Al|Bh = 30720
#define SMEM_SZ3 (ST3 * STAGEB3)        // 92160 (epilogue overlays)

__global__ __launch_bounds__(256, 1) void gemm_2p_scale(
    const __half* __restrict__ Ah_g, const __half* __restrict__ Al_g,
    const __half* __restrict__ Bh_g,
    float* __restrict__ O1, __nv_bfloat16* __restrict__ Ob, int P)
{
    extern __shared__ char smraw[];
    const uint32_t sb = smem_u32(smraw);

    const int tid = threadIdx.x, lane = tid & 31, wid = tid >> 5;
    const int wm = wid >> 1, wn = wid & 1;
    const int bx = blockIdx.x, by = blockIdx.y;

    const __half* At_h = Ah_g + (size_t)(by * BM) * P;
    const __half* At_l = Al_g + (size_t)(by * BM) * P;
    const __half* Bt_h = Bh_g + (size_t)(bx * BN) * P;
    const int iters = P / BK;

    const int crow = tid >> 1;
    const int cch  = (tid & 1) * 2;
    const int a_row  = wm * 32 + (lane & 15);
    const int a_koff = (lane >> 4) << 3;
    const int b_n    = wn * 64 + ((lane >> 4) << 3) + (lane & 7);
    const int b_koff = ((lane >> 3) & 1) << 3;

    float acc[2][8][4];
#pragma unroll
    for (int mt = 0; mt < 2; mt++)
#pragma unroll
        for (int nt = 0; nt < 8; nt++)
#pragma unroll
            for (int i = 0; i < 4; i++) acc[mt][nt][i] = 0.0f;

    auto issue = [&](int s, int k0) {
        const uint32_t st = sb + (uint32_t)(s * STAGEB3);
#pragma unroll
        for (int c = 0; c < 2; c++) {
            uint32_t off = (uint32_t)(crow * ROWB + (cch + c) * 16);
            size_t go = (size_t)crow * P + k0 + (cch + c) * 8;
            CP16(st + off,             At_h + go);
            CP16(st + TILEB + off,     At_l + go);
            CP16(st + 2 * TILEB + off, Bt_h + go);
        }
    };

#pragma unroll
    for (int s = 0; s < ST3 - 1; s++) { issue(s, s * BK); CP_COMMIT(); }

    for (int t = 0; t < iters; ++t) {
        CP_WAIT(ST3 - 2);
        __syncthreads();
        if (t + ST3 - 1 < iters) issue((t + ST3 - 1) % ST3, (t + ST3 - 1) * BK);
        CP_COMMIT();

        const uint32_t stage = sb + (uint32_t)((t % ST3) * STAGEB3);
#pragma unroll
        for (int ch = 0; ch < 2; ch++) {
            uint32_t Ahf[2][4], Alf[2][4], Bhf[8][2];
#pragma unroll
            for (int mt = 0; mt < 2; mt++) {
                uint32_t addr = stage +
                    (uint32_t)((a_row + mt * 16) * ROWB + (ch * 16 + a_koff) * 2);
                ldsm4(Ahf[mt], addr);
                ldsm4(Alf[mt], addr + TILEB);
            }
#pragma unroll
            for (int q = 0; q < 4; q++) {
                uint32_t addr = stage + 2 * TILEB +
                    (uint32_t)((b_n + q * 16) * ROWB + (ch * 16 + b_koff) * 2);
                uint32_t r[4];
                ldsm4(r, addr);
                Bhf[q * 2][0] = r[0]; Bhf[q * 2][1] = r[1];
                Bhf[q * 2 + 1][0] = r[2]; Bhf[q * 2 + 1][1] = r[3];
            }
#pragma unroll
            for (int mt = 0; mt < 2; mt++)
#pragma unroll
                for (int nt = 0; nt < 8; nt++) {
                    mma_f16(acc[mt][nt], Ahf[mt], Bhf[nt]);
                    mma_f16(acc[mt][nt], Alf[mt], Bhf[nt]);
                }
        }
    }
    CP_WAIT(0);
    __syncthreads();

    // epilogue: scale rows; fp32 -> O1 (d_out, maybe unaligned) + bf16 Wm hi
    float* smC = (float*)smraw;   // [128][129]
#pragma unroll
    for (int mt = 0; mt < 2; mt++)
#pragma unroll
        for (int nt = 0; nt < 8; nt++) {
            int r0 = wm * 32 + mt * 16 + (lane >> 2);
            int c0 = wn * 64 + nt * 8 + (lane & 3) * 2;
            smC[r0 * 129 + c0]           = acc[mt][nt][0];
            smC[r0 * 129 + c0 + 1]       = acc[mt][nt][1];
            smC[(r0 + 8) * 129 + c0]     = acc[mt][nt][2];
            smC[(r0 + 8) * 129 + c0 + 1] = acc[mt][nt][3];
        }
    __syncthreads();

    const double s = g_s;
    for (int it = 0; it < 16; it++) {
        int f = it * 256 + tid;
        int row = f >> 5, c4 = (f & 31) * 4;
        double w = (double)g_W[by * BM + row];
        double w2 = w * w;
        float sc = (float)(w2 / (s * w2 + 1.0));
        float4 v;
        v.x = smC[row * 129 + c4] * sc;
        v.y = smC[row * 129 + c4 + 1] * sc;
        v.z = smC[row * 129 + c4 + 2] * sc;
        v.w = smC[row * 129 + c4 + 3] * sc;
        size_t gi = (size_t)(by * BM + row) * P + bx * BN + c4;
        if (O1) {
            O1[gi] = v.x; O1[gi + 1] = v.y; O1[gi + 2] = v.z; O1[gi + 3] = v.w;
        }
        *(uint2*)(Ob + gi) = make_uint2(cvt2bf(v.x, v.y), cvt2bf(v.z, v.w));
    }
}

// ================= single-pass bf16 GEMM, 4-stage cp.async =================
#define ST1 4
#define STAGEB1 (2 * TILEB)             // Ah|Bh = 20480
#define SMEM_SZ1 (ST1 * STAGEB1)        // 81920 (epilogue overlays)

// MODE 2: D - aux -> bf16 transposed O0;  MODE 3: g_ss += sum(D^2)
template <int MODE>
__global__ __launch_bounds__(256, 2) void gemm_1p(
    const __nv_bfloat16* __restrict__ A, const __nv_bfloat16* __restrict__ B,
    const float* __restrict__ aux, __nv_bfloat16* __restrict__ O0, int P)
{
    extern __shared__ char smraw[];
    const uint32_t sb = smem_u32(smraw);

    const int tid = threadIdx.x, lane = tid & 31, wid = tid >> 5;
    const int wm = wid >> 1, wn = wid & 1;
    const int bx = blockIdx.x, by = blockIdx.y;

    const __nv_bfloat16* At = A + (size_t)(by * BM) * P;
    const __nv_bfloat16* Bt = B + (size_t)(bx * BN) * P;
    const int iters = P / BK;

    const int crow = tid >> 1;
    const int cch  = (tid & 1) * 2;
    const int a_row  = wm * 32 + (lane & 15);
    const int a_koff = (lane >> 4) << 3;
    const int b_n    = wn * 64 + ((lane >> 4) << 3) + (lane & 7);
    const int b_koff = ((lane >> 3) & 1) << 3;

    float acc[2][8][4];
#pragma unroll
    for (int mt = 0; mt < 2; mt++)
#pragma unroll
        for (int nt = 0; nt < 8; nt++)
#pragma unroll
            for (int i = 0; i < 4; i++) acc[mt][nt][i] = 0.0f;

    auto issue = [&](int s, int k0) {
        const uint32_t st = sb + (uint32_t)(s * STAGEB1);
#pragma unroll
        for (int c = 0; c < 2; c++) {
            uint32_t off = (uint32_t)(crow * ROWB + (cch + c) * 16);
            size_t go = (size_t)crow * P + k0 + (cch + c) * 8;
            CP16(st + off,         At + go);
            CP16(st + TILEB + off, Bt + go);
        }
    };

#pragma unroll
    for (int s = 0; s < ST1 - 1; s++) { issue(s, s * BK); CP_COMMIT(); }

    for (int t = 0; t < iters; ++t) {
        CP_WAIT(ST1 - 2);
        __syncthreads();
        if (t + ST1 - 1 < iters) issue((t + ST1 - 1) % ST1, (t + ST1 - 1) * BK);
        CP_COMMIT();

        const uint32_t stage = sb + (uint32_t)((t % ST1) * STAGEB1);
#pragma unroll
        for (int ch = 0; ch < 2; ch++) {
            uint32_t Ahf[2][4], Bhf[8][2];
#pragma unroll
            for (int mt = 0; mt < 2; mt++) {
                uint32_t addr = stage +
                    (uint32_t)((a_row + mt * 16) * ROWB + (ch * 16 + a_koff) * 2);
                ldsm4(Ahf[mt], addr);
            }
#pragma unroll
            for (int q = 0; q < 4; q++) {
                uint32_t addr = stage + TILEB +
                    (uint32_t)((b_n + q * 16) * ROWB + (ch * 16 + b_koff) * 2);
                uint32_t r[4];
                ldsm4(r, addr);
                Bhf[q * 2][0] = r[0]; Bhf[q * 2][1] = r[1];
                Bhf[q * 2 + 1][0] = r[2]; Bhf[q * 2 + 1][1] = r[3];
            }
#pragma unroll
            for (int mt = 0; mt < 2; mt++)
#pragma unroll
                for (int nt = 0; nt < 8; nt++)
                    mma_bf16(acc[mt][nt], Ahf[mt], Bhf[nt]);
        }
    }
    CP_WAIT(0);
    __syncthreads();

    if (MODE == 3) {
        float local = 0.0f;
#pragma unroll
        for (int mt = 0; mt < 2; mt++)
#pragma unroll
            for (int nt = 0; nt < 8; nt++)
#pragma unroll
                for (int i = 0; i < 4; i++)
                    local += acc[mt][nt][i] * acc[mt][nt][i];
        float bsum = blockReduceSum(local);
        if (tid == 0) atomicAdd(&g_ss, (double)bsum);
        return;
    }

    // MODE 2: subtract aux, store transposed bf16
    float* smC = (float*)smraw;   // [128][129]
#pragma unroll
    for (int mt = 0; mt < 2; mt++)
#pragma unroll
        for (int nt = 0; nt < 8; nt++) {
            int r0 = wm * 32 + mt * 16 + (lane >> 2);
            int c0 = wn * 64 + nt * 8 + (lane & 3) * 2;
            smC[r0 * 129 + c0]           = acc[mt][nt][0];
            smC[r0 * 129 + c0 + 1]       = acc[mt][nt][1];
            smC[(r0 + 8) * 129 + c0]     = acc[mt][nt][2];
            smC[(r0 + 8) * 129 + c0 + 1] = acc[mt][nt][3];
        }
    __syncthreads();

    for (int it = 0; it < 16; it++) {
        int f = it * 256 + tid;
        int row = f >> 5, c4 = (f & 31) * 4;
        float4 sv = *(const float4*)(aux + (size_t)(by * BM + row) * P + bx * BN + c4);
        smC[row * 129 + c4]     -= sv.x;
        smC[row * 129 + c4 + 1] -= sv.y;
        smC[row * 129 + c4 + 2] -= sv.z;
        smC[row * 129 + c4 + 3] -= sv.w;
    }
    __syncthreads();
    for (int it = 0; it < 16; it++) {
        int f = it * 256 + tid;
        int n = f >> 5, m4 = (f & 31) * 4;
        uint2 pk;
        pk.x = cvt2bf(smC[(m4 + 0) * 129 + n], smC[(m4 + 1) * 129 + n]);
        pk.y = cvt2bf(smC[(m4 + 2) * 129 + n], smC[(m4 + 3) * 129 + n]);
        *(uint2*)(O0 + (size_t)(bx * BN + n) * P + by * BM + m4) = pk;
    }
}

// ---------------- launch ---------------------------------------------------
extern "C" void kernel_launch(void* const* d_in, const int* in_sizes, int n_in,
                              void* d_out, int out_size)
{
    const float* target = (const float*)d_in[0];
    const float* source = (const float*)d_in[1];
    const float* Wb     = (const float*)d_in[2];
    float* out = (float*)d_out;

    int P = (int)(sqrt((double)in_sizes[0]) + 0.5);
    size_t pp = (size_t)P * P;

    bool has_matrix = (size_t)out_size >= pp;
    bool has_loss   = ((size_t)out_size != pp);
    float* outW = has_matrix ? (out + (out_size - (int)pp)) : nullptr;

    __half *shi, *slo, *thi;
    __nv_bfloat16 *wbh, *ttb, *wmh, *prb;
    cudaGetSymbolAddress((void**)&shi, g_Shi);
    cudaGetSymbolAddress((void**)&slo, g_Slo);
    cudaGetSymbolAddress((void**)&thi, g_Thi);
    cudaGetSymbolAddress((void**)&wbh, g_Wbh);
    cudaGetSymbolAddress((void**)&ttb, g_Ttb);
    cudaGetSymbolAddress((void**)&wmh, g_Wmh);
    cudaGetSymbolAddress((void**)&prb, g_PrTb);

    cudaFuncSetAttribute(gemm_2p_scale, cudaFuncAttributeMaxDynamicSharedMemorySize, SMEM_SZ3);
    cudaFuncSetAttribute(gemm_1p<2>, cudaFuncAttributeMaxDynamicSharedMemorySize, SMEM_SZ1);
    cudaFuncSetAttribute(gemm_1p<3>, cudaFuncAttributeMaxDynamicSharedMemorySize, SMEM_SZ1);

    init_kernel<<<1, 1>>>();
    split_f16_kernel<<<1024, 256>>>(source, shi, slo, pp / 4);
    thi_sumsq_kernel<<<1024, 256>>>(target, thi, pp / 4);
    wb_convert_kernel<<<P, 256>>>(Wb, wbh, P);
    transpose_bf16_kernel<<<dim3(P / 32, P / 32), dim3(32, 8)>>>(target, ttb, P);

    dim3 grid(P / BN, P / BM);
    // Wm = scale .* (source @ target^T)   [fp16 2-pass]
    gemm_2p_scale<<<grid, 256, SMEM_SZ3>>>(shi, slo, thi, outW, wmh, P);
    // primary^T (bf16) = (Wm @ target - source)^T   [1-pass]
    gemm_1p<2><<<grid, 256, SMEM_SZ1>>>(wmh, ttb, source, prb, P);
    // ss += ||W_beta @ primary||^2                   [1-pass]
    gemm_1p<3><<<grid, 256, SMEM_SZ1>>>(wbh, prb, nullptr, nullptr, P);

    if (has_loss) finalize_kernel<<<1, 1>>>(out);
}